// round 13
// baseline (speedup 1.0000x reference)
#include <cuda_runtime.h>
#include <cuda_bf16.h>
#include <math.h>
#include <stdint.h>

// Problem constants
#define T_TOK   8192
#define DDIM    1024
#define HDIM    4096
#define NEXP    8
#define KSEL    1024

// ---------------- device scratch ----------------
// Packed operand layout (A and B of MMA):
//   element (row r, col k): kb=k>>3, rb=r>>3, h=(k>>2)&1, rr=r&7, kk=k&3
//   float offset = (((kb*RB + rb)*2 + h)*8 + rr)*4 + kk   (RB = rows/8)
__device__ double g_probs[NEXP * T_TOK];
__device__ int    g_sel[NEXP * KSEL];
__device__ float  g_wts[NEXP * KSEL];
__device__ float  g_xg [(size_t)NEXP * KSEL * DDIM];
__device__ float  g_h  [(size_t)NEXP * KSEL * HDIM];
__device__ float  g_w1r[(size_t)NEXP * DDIM * HDIM];
__device__ float  g_w2r[(size_t)NEXP * HDIM * DDIM];
__device__ unsigned long long g_key0[NEXP * 8192];

__device__ __forceinline__ uint32_t smem_u32(const void* p) {
    uint32_t a;
    asm("{ .reg .u64 t; cvta.to.shared.u64 t, %1; cvt.u32.u64 %0, t; }" : "=r"(a) : "l"(p));
    return a;
}
__device__ __forceinline__ void cpasync16(uint32_t dst, const void* src) {
    asm volatile("cp.async.cg.shared.global [%0], [%1], 16;" :: "r"(dst), "l"(src) : "memory");
}
__device__ __forceinline__ float tf32_rna(float v) {
    uint32_t o;
    asm("cvt.rna.tf32.f32 %0, %1;" : "=r"(o) : "f"(v));
    return __uint_as_float(o);
}
__device__ __forceinline__ float gelu_exact(float v) {
    return 0.5f * v * (1.0f + erff(v * 0.7071067811865476f));
}
__device__ __forceinline__ void ldsm_x4(uint32_t* r, uint32_t addr) {
    asm volatile("ldmatrix.sync.aligned.m8n8.x4.shared.b16 {%0,%1,%2,%3}, [%4];"
                 : "=r"(r[0]), "=r"(r[1]), "=r"(r[2]), "=r"(r[3]) : "r"(addr));
}
__device__ __forceinline__ void mma_16n8k8(float* d, const uint32_t* a, const uint32_t* b) {
    asm volatile(
        "mma.sync.aligned.m16n8k8.row.col.f32.tf32.tf32.f32 "
        "{%0,%1,%2,%3},{%4,%5,%6,%7},{%8,%9},{%0,%1,%2,%3};"
        : "+f"(d[0]), "+f"(d[1]), "+f"(d[2]), "+f"(d[3])
        : "r"(a[0]), "r"(a[1]), "r"(a[2]), "r"(a[3]), "r"(b[0]), "r"(b[1]));
}

// ================= router (fp64) =================
__global__ void router_kernel(const float* __restrict__ x,
                              const float* __restrict__ rw,
                              float* __restrict__ logits_out) {
    const int t = blockIdx.x;
    const int tid = threadIdx.x;
    const float* xr = x + (size_t)t * DDIM;
    double acc[NEXP];
#pragma unroll
    for (int e = 0; e < NEXP; e++) acc[e] = 0.0;
    const int k = tid * 4;
    float4 xv = *(const float4*)(xr + k);
#pragma unroll
    for (int e = 0; e < NEXP; e++) {
        float4 wv = *(const float4*)(rw + e * DDIM + k);
        acc[e] = fma((double)xv.x, (double)wv.x, acc[e]);
        acc[e] = fma((double)xv.y, (double)wv.y, acc[e]);
        acc[e] = fma((double)xv.z, (double)wv.z, acc[e]);
        acc[e] = fma((double)xv.w, (double)wv.w, acc[e]);
    }
#pragma unroll
    for (int e = 0; e < NEXP; e++)
#pragma unroll
        for (int o = 16; o; o >>= 1)
            acc[e] += __shfl_xor_sync(0xffffffffu, acc[e], o);
    __shared__ double red[NEXP][8];
    const int wid = tid >> 5, lid = tid & 31;
    if (lid == 0)
#pragma unroll
        for (int e = 0; e < NEXP; e++) red[e][wid] = acc[e];
    __syncthreads();
    if (tid == 0) {
        double l[NEXP], mx = -1e300;
#pragma unroll
        for (int e = 0; e < NEXP; e++) {
            double s = 0.0;
#pragma unroll
            for (int w = 0; w < 8; w++) s += red[e][w];
            l[e] = s; mx = fmax(mx, s);
        }
        double p[NEXP], sum = 0.0;
#pragma unroll
        for (int e = 0; e < NEXP; e++) { p[e] = exp(l[e] - mx); sum += p[e]; }
#pragma unroll
        for (int e = 0; e < NEXP; e++) {
            if (logits_out) logits_out[(size_t)t * NEXP + e] = (float)l[e];
            g_probs[(size_t)e * T_TOK + t] = p[e] / sum;
        }
    }
}

// ================= topk phase 1: sort 1024-chunks descending =================
__global__ void sort1024_kernel() {
    __shared__ unsigned long long key[1024];
    const int b = blockIdx.x;            // 64 blocks
    const int e = b >> 3, c = b & 7;
    const int tid = threadIdx.x;         // 512
#pragma unroll
    for (int q = 0; q < 2; q++) {
        const int i = tid + q * 512;
        const int gi = c * 1024 + i;
        double p = g_probs[(size_t)e * T_TOK + gi];
        unsigned long long db = __double_as_longlong(p);
        key[i] = (db & ~0x1FFFULL) | (unsigned long long)(8191 - gi);
    }
    __syncthreads();
    for (int k = 2; k <= 1024; k <<= 1) {
        for (int j = k >> 1; j > 0; j >>= 1) {
            const int i = ((tid & ~(j - 1)) << 1) | (tid & (j - 1));
            const int l = i | j;
            unsigned long long a = key[i], bb = key[l];
            bool descend = ((i & k) == 0);
            if ((a < bb) == descend) { key[i] = bb; key[l] = a; }
            __syncthreads();
        }
    }
    g_key0[(size_t)e * 8192 + c * 1024 + tid] = key[tid];
    g_key0[(size_t)e * 8192 + c * 1024 + tid + 512] = key[tid + 512];
}

// ================= topk phase 2: full merge tree per expert =================
__global__ void merge_tree_kernel(float* __restrict__ sel_out) {
    __shared__ unsigned long long buf[4][1024];
    __shared__ unsigned long long c[1024];
    const int e = blockIdx.x;
    const int tid = threadIdx.x;         // 512

    auto bitonic_desc = [&]() {
        for (int j = 512; j > 0; j >>= 1) {
            const int i = ((tid & ~(j - 1)) << 1) | (tid & (j - 1));
            const int l = i | j;
            unsigned long long x = c[i], y = c[l];
            if (x < y) { c[i] = y; c[l] = x; }
            __syncthreads();
        }
    };

#pragma unroll 1
    for (int p = 0; p < 4; p++) {
        const unsigned long long* A = g_key0 + (size_t)e * 8192 + (size_t)(2 * p) * 1024;
        const unsigned long long* B = A + 1024;
        unsigned long long a0 = A[tid], b0 = B[1023 - tid];
        c[tid] = a0 > b0 ? a0 : b0;
        unsigned long long a1 = A[tid + 512], b1 = B[511 - tid];
        c[tid + 512] = a1 > b1 ? a1 : b1;
        __syncthreads();
        bitonic_desc();
        buf[p][tid] = c[tid];
        buf[p][tid + 512] = c[tid + 512];
        __syncthreads();
    }
#pragma unroll 1
    for (int p = 0; p < 2; p++) {
        unsigned long long a0 = buf[2 * p][tid],       b0 = buf[2 * p + 1][1023 - tid];
        unsigned long long a1 = buf[2 * p][tid + 512], b1 = buf[2 * p + 1][511 - tid];
        c[tid] = a0 > b0 ? a0 : b0;
        c[tid + 512] = a1 > b1 ? a1 : b1;
        __syncthreads();
        bitonic_desc();
        buf[p][tid] = c[tid];
        buf[p][tid + 512] = c[tid + 512];
        __syncthreads();
    }
    {
        unsigned long long a0 = buf[0][tid],       b0 = buf[1][1023 - tid];
        unsigned long long a1 = buf[0][tid + 512], b1 = buf[1][511 - tid];
        c[tid] = a0 > b0 ? a0 : b0;
        c[tid + 512] = a1 > b1 ? a1 : b1;
        __syncthreads();
        bitonic_desc();
    }
#pragma unroll
    for (int q = 0; q < 2; q++) {
        const int i = tid + q * 512;
        unsigned long long kk = c[i];
        int idx = 8191 - (int)(kk & 0x1FFFULL);
        double val = __longlong_as_double((long long)(kk & ~0x1FFFULL));
        g_sel[e * KSEL + i] = idx;
        g_wts[e * KSEL + i] = (float)val;
        if (sel_out) sel_out[e * KSEL + i] = (float)idx;
    }
}

// ================= gather A rows -> packed layout + rna =================
__global__ void gather_x_kernel(const float* __restrict__ x) {
    const int row = blockIdx.x;                 // 0..8191
    const int e = row >> 10, i = row & 1023;
    const int tok = g_sel[e * KSEL + i];
    const int tid = threadIdx.x;                // 0..255
    float4 v = ((const float4*)(x + (size_t)tok * DDIM))[tid];
    v.x = tf32_rna(v.x); v.y = tf32_rna(v.y);
    v.z = tf32_rna(v.z); v.w = tf32_rna(v.w);
    const int kb = tid >> 1, h = tid & 1;
    const int rb = i >> 3, rr = i & 7;
    const size_t off = ((((size_t)e * 128 + kb) * 128 + rb) * 2 + h) * 32 + rr * 4;
    *(float4*)(g_xg + off) = v;
}

// ================= weight pack: [E][K][N] -> packed(r=n, k) + rna =================
__global__ void pack_w_kernel(const float* __restrict__ src, float* __restrict__ dst,
                              int K, int N) {
    __shared__ float t[32][33];
    const int e = blockIdx.z;
    const int k0 = blockIdx.y * 32, n0 = blockIdx.x * 32;
    const int tx = threadIdx.x, ty = threadIdx.y;
    const float* s = src + (size_t)e * K * N;
#pragma unroll
    for (int j = 0; j < 4; j++)
        t[ty + 8 * j][tx] = s[(size_t)(k0 + ty + 8 * j) * N + n0 + tx];
    __syncthreads();
    float4 v;
    v.x = tf32_rna(t[ty * 4 + 0][tx]);
    v.y = tf32_rna(t[ty * 4 + 1][tx]);
    v.z = tf32_rna(t[ty * 4 + 2][tx]);
    v.w = tf32_rna(t[ty * 4 + 3][tx]);
    const int n = n0 + tx, kv = k0 + ty * 4;
    const int kb = kv >> 3, h = (kv >> 2) & 1;
    const int nb = n >> 3, nn = n & 7;
    const size_t KB = (size_t)(K >> 3), NB = (size_t)(N >> 3);
    const size_t off = ((((size_t)e * KB + kb) * NB + nb) * 2 + h) * 32 + nn * 4;
    *(float4*)(dst + off) = v;
}

// ================= mma.m16n8k8 tf32 GEMM, CTA 128x128, warp 64x32 =================
// KSPLIT: split the K reduction across KSPLIT CTAs (partials combined by the
// epilogue's atomicAdd; bias added only by split 0). GEMM1 uses KSPLIT=1.
#define BM   128
#define BN   128
#define LDC  132
#define STAGES 3

#define OFF_TOK   0                  // 128 ints
#define OFF_WT    512                // 128 floats
#define OFF_BIAS  1024               // 128 floats
#define OFF_DATA  2048
#define A_BYTES_S 16384
#define STAGE_SZ  32768
#define GEMM_SMEM (OFF_DATA + STAGES * STAGE_SZ)   // 100352

template <bool G1, int KSPLIT>
__global__ __launch_bounds__(256, 2)
void moe_mma_kernel(const float* __restrict__ Bw,     // packed weights
                    const float* __restrict__ bias,   // [E][N]
                    float* __restrict__ res) {
    extern __shared__ char smem[];
    const uint32_t sb = smem_u32(smem);
    const int tid = threadIdx.x;
    const int lane = tid & 31;
    const int e = blockIdx.z / KSPLIT, sp = blockIdx.z % KSPLIT;
    const int by = blockIdx.y, bx = blockIdx.x;

    constexpr int KDIM = G1 ? DDIM : HDIM;
    constexpr int NTOT = G1 ? HDIM : DDIM;
    constexpr int KI = KDIM / 32 / KSPLIT;      // K-iters per CTA
    constexpr int RB = 128;
    constexpr int NB = NTOT / 8;

    const float* A = (G1 ? g_xg : g_h) + (size_t)e * KDIM * 1024;
    const float* B = Bw + (size_t)e * KDIM * NTOT;
    const int kt0 = sp * KI;

    if (tid < 128) {
        ((float*)(smem + OFF_BIAS))[tid] =
            (sp == 0) ? bias[e * NTOT + bx * BN + tid] : 0.0f;
        if (!G1) {
            ((int*)(smem + OFF_TOK))[tid] = g_sel[e * KSEL + by * BM + tid];
            ((float*)(smem + OFF_WT))[tid] = g_wts[e * KSEL + by * BM + tid];
        }
    }

    auto load_stage = [&](int kt, int buf) {
        const uint32_t st = sb + OFF_DATA + buf * STAGE_SZ;
#pragma unroll
        for (int i = 0; i < 8; i++) {
            const int c = tid + 256 * i;         // 0..2047
            const int kb = (c >> 8) & 3, inner = c & 255;
            const float* src;
            if (c < 1024)
                src = A + ((size_t)(kt * 4 + kb) * RB + by * 16) * 64 + inner * 4;
            else
                src = B + ((size_t)(kt * 4 + kb) * NB + bx * 16) * 64 + inner * 4;
            cpasync16(st + c * 16, src);
        }
        asm volatile("cp.async.commit_group;" ::: "memory");
    };

    const int wid = tid >> 5;
    const int wm = wid & 1, wn = wid >> 1;
    const int msel = lane >> 3;
    const uint32_t aoff = (uint32_t)(((msel & 1) * 16 + (msel >> 1) * 8 + (lane & 7)));
    const uint32_t boff = (uint32_t)(((msel >> 1) * 16 + (msel & 1) * 8 + (lane & 7)));
    const uint32_t aWarp = (uint32_t)(wm * 8 * 16 + aoff) * 16;
    const uint32_t bWarp = (uint32_t)A_BYTES_S + ((uint32_t)(wn * 4 * 16 + boff) * 16);

    float acc[4][4][4];
#pragma unroll
    for (int i = 0; i < 4; i++)
#pragma unroll
        for (int j = 0; j < 4; j++)
#pragma unroll
            for (int q = 0; q < 4; q++) acc[i][j][q] = 0.f;

    load_stage(kt0 + 0, 0);
    load_stage(kt0 + 1, 1);

    int buf = 0;
#pragma unroll 1
    for (int kt = 0; kt < KI; kt++) {
        if (kt < KI - 1) asm volatile("cp.async.wait_group 1;" ::: "memory");
        else             asm volatile("cp.async.wait_group 0;" ::: "memory");
        __syncthreads();
        if (kt + 2 < KI) {
            int nb2 = buf + 2; if (nb2 >= STAGES) nb2 -= STAGES;
            load_stage(kt0 + kt + 2, nb2);
        }
        const uint32_t st = sb + OFF_DATA + buf * STAGE_SZ;
#pragma unroll
        for (int ks = 0; ks < 4; ks++) {
            const uint32_t ksb = st + ks * 4096;
            uint32_t a[4][4], b[4][2];
#pragma unroll
            for (int mt = 0; mt < 4; mt++)
                ldsm_x4(a[mt], ksb + aWarp + mt * 512);
#pragma unroll
            for (int p = 0; p < 2; p++) {
                uint32_t r[4];
                ldsm_x4(r, ksb + bWarp + p * 512);
                b[2 * p][0] = r[0]; b[2 * p][1] = r[1];
                b[2 * p + 1][0] = r[2]; b[2 * p + 1][1] = r[3];
            }
#pragma unroll
            for (int mt = 0; mt < 4; mt++)
#pragma unroll
                for (int nt = 0; nt < 4; nt++)
                    mma_16n8k8(acc[mt][nt], a[mt], b[nt]);
        }
        if (++buf == STAGES) buf = 0;
    }
    __syncthreads();

    // ---- stage C through smem ----
    float* Cs = (float*)(smem + OFF_DATA);
#pragma unroll
    for (int mt = 0; mt < 4; mt++)
#pragma unroll
        for (int nt = 0; nt < 4; nt++) {
            const int r0 = wm * 64 + mt * 16 + (lane >> 2);
            const int cc = wn * 32 + nt * 8 + (lane & 3) * 2;
            *(float2*)&Cs[r0 * LDC + cc]       = make_float2(acc[mt][nt][0], acc[mt][nt][1]);
            *(float2*)&Cs[(r0 + 8) * LDC + cc] = make_float2(acc[mt][nt][2], acc[mt][nt][3]);
        }
    __syncthreads();

    const float* sbias = (const float*)(smem + OFF_BIAS);
    if (G1) {
#pragma unroll
        for (int q = 0; q < 16; q++) {
            const int v = tid * 16 + q;
            const int r = v >> 5, c4 = (v & 31) * 4;
            float4 c = *(const float4*)(Cs + r * LDC + c4);
            c.x = tf32_rna(gelu_exact(c.x + sbias[c4 + 0]));
            c.y = tf32_rna(gelu_exact(c.y + sbias[c4 + 1]));
            c.z = tf32_rna(gelu_exact(c.z + sbias[c4 + 2]));
            c.w = tf32_rna(gelu_exact(c.w + sbias[c4 + 3]));
            const int n = bx * BN + c4;
            const int kb = n >> 3, h = (n >> 2) & 1;
            const int m = by * BM + r;
            const int rb = m >> 3, rr = m & 7;
            const size_t off = ((((size_t)e * 512 + kb) * 128 + rb) * 2 + h) * 32 + rr * 4;
            *(float4*)(g_h + off) = c;
        }
    } else {
        const int* tok = (const int*)(smem + OFF_TOK);
        const float* wts = (const float*)(smem + OFF_WT);
#pragma unroll
        for (int q = 0; q < 16; q++) {
            const int v = tid * 16 + q;
            const int r = v >> 5, c4 = (v & 31) * 4;
            float4 c = *(const float4*)(Cs + r * LDC + c4);
            const float g = wts[r];
            float* dst = res + (size_t)tok[r] * DDIM + bx * BN + c4;
            atomicAdd(dst + 0, (c.x + sbias[c4 + 0]) * g);
            atomicAdd(dst + 1, (c.y + sbias[c4 + 1]) * g);
            atomicAdd(dst + 2, (c.z + sbias[c4 + 2]) * g);
            atomicAdd(dst + 3, (c.w + sbias[c4 + 3]) * g);
        }
    }
}

// ================= launch =================
extern "C" void kernel_launch(void* const* d_in, const int* in_sizes, int n_in,
                              void* d_out, int out_size) {
    const float* x  = (const float*)d_in[0];
    const float* rw = (const float*)d_in[1];
    const float* w1 = (const float*)d_in[2];
    const float* b1 = (const float*)d_in[3];
    const float* w2 = (const float*)d_in[4];
    const float* b2 = (const float*)d_in[5];

    float* out = (float*)d_out;
    float* res = out;
    float* logits_out = nullptr;
    float* sel_out = nullptr;
    const long long TD = (long long)T_TOK * DDIM;
    if (out_size >= TD + T_TOK * NEXP) logits_out = out + TD;
    if (out_size >= TD + T_TOK * NEXP + NEXP * KSEL) sel_out = out + TD + T_TOK * NEXP;

    static cudaStream_t sw1 = nullptr, sw2 = nullptr;
    static cudaEvent_t ev0 = nullptr, ev1 = nullptr, ev2 = nullptr;
    if (!sw1) {
        cudaStreamCreateWithFlags(&sw1, cudaStreamNonBlocking);
        cudaStreamCreateWithFlags(&sw2, cudaStreamNonBlocking);
        cudaEventCreateWithFlags(&ev0, cudaEventDisableTiming);
        cudaEventCreateWithFlags(&ev1, cudaEventDisableTiming);
        cudaEventCreateWithFlags(&ev2, cudaEventDisableTiming);
    }

    float* w1r; cudaGetSymbolAddress((void**)&w1r, g_w1r);
    float* w2r; cudaGetSymbolAddress((void**)&w2r, g_w2r);

    cudaFuncSetAttribute((const void*)moe_mma_kernel<true, 1>,
                         cudaFuncAttributeMaxDynamicSharedMemorySize, GEMM_SMEM);
    cudaFuncSetAttribute((const void*)moe_mma_kernel<false, 4>,
                         cudaFuncAttributeMaxDynamicSharedMemorySize, GEMM_SMEM);

    // fork: weight packing + memset(res) on side streams
    cudaEventRecord(ev0, 0);
    cudaStreamWaitEvent(sw1, ev0, 0);
    cudaStreamWaitEvent(sw2, ev0, 0);
    pack_w_kernel<<<dim3(HDIM / 32, DDIM / 32, NEXP), dim3(32, 8), 0, sw1>>>(w1, w1r, DDIM, HDIM);
    cudaMemsetAsync(res, 0, (size_t)TD * sizeof(float), sw2);
    pack_w_kernel<<<dim3(DDIM / 32, HDIM / 32, NEXP), dim3(32, 8), 0, sw2>>>(w2, w2r, HDIM, DDIM);
    cudaEventRecord(ev1, sw1);
    cudaEventRecord(ev2, sw2);

    // main stream: router -> topk (sort + merge tree) -> gather
    router_kernel<<<T_TOK, 256>>>(x, rw, logits_out);
    sort1024_kernel<<<64, 512>>>();
    merge_tree_kernel<<<NEXP, 512>>>(sel_out);
    gather_x_kernel<<<NEXP * KSEL, 256>>>(x);

    // GEMM1 (no K-split), then GEMM2 with K-split 4 (2048 CTAs, clean waves)
    cudaStreamWaitEvent(0, ev1, 0);
    moe_mma_kernel<true, 1><<<dim3(HDIM / BN, KSEL / BM, NEXP), 256, GEMM_SMEM>>>(w1r, b1, nullptr);
    cudaStreamWaitEvent(0, ev2, 0);
    moe_mma_kernel<false, 4><<<dim3(DDIM / BN, KSEL / BM, NEXP * 4), 256, GEMM_SMEM>>>(w2r, b2, res);
}

// round 14
// speedup vs baseline: 1.0421x; 1.0421x over previous
#include <cuda_runtime.h>
#include <cuda_bf16.h>
#include <math.h>
#include <stdint.h>

// Problem constants
#define T_TOK   8192
#define DDIM    1024
#define HDIM    4096
#define NEXP    8
#define KSEL    1024

// ---------------- device scratch ----------------
// Packed operand layout (A and B of MMA):
//   element (row r, col k): kb=k>>3, rb=r>>3, h=(k>>2)&1, rr=r&7, kk=k&3
//   float offset = (((kb*RB + rb)*2 + h)*8 + rr)*4 + kk   (RB = rows/8)
__device__ double g_probs[NEXP * T_TOK];
__device__ int    g_sel[NEXP * KSEL];
__device__ float  g_wts[NEXP * KSEL];
__device__ float  g_xg [(size_t)NEXP * KSEL * DDIM];
__device__ float  g_h  [(size_t)NEXP * KSEL * HDIM];
__device__ float  g_w1r[(size_t)NEXP * DDIM * HDIM];
__device__ float  g_w2r[(size_t)NEXP * HDIM * DDIM];
__device__ unsigned long long g_key0[NEXP * 8192];

__device__ __forceinline__ uint32_t smem_u32(const void* p) {
    uint32_t a;
    asm("{ .reg .u64 t; cvta.to.shared.u64 t, %1; cvt.u32.u64 %0, t; }" : "=r"(a) : "l"(p));
    return a;
}
__device__ __forceinline__ void cpasync16(uint32_t dst, const void* src) {
    asm volatile("cp.async.cg.shared.global [%0], [%1], 16;" :: "r"(dst), "l"(src) : "memory");
}
__device__ __forceinline__ float tf32_rna(float v) {
    uint32_t o;
    asm("cvt.rna.tf32.f32 %0, %1;" : "=r"(o) : "f"(v));
    return __uint_as_float(o);
}
__device__ __forceinline__ float gelu_exact(float v) {
    return 0.5f * v * (1.0f + erff(v * 0.7071067811865476f));
}
__device__ __forceinline__ void ldsm_x4(uint32_t* r, uint32_t addr) {
    asm volatile("ldmatrix.sync.aligned.m8n8.x4.shared.b16 {%0,%1,%2,%3}, [%4];"
                 : "=r"(r[0]), "=r"(r[1]), "=r"(r[2]), "=r"(r[3]) : "r"(addr));
}
__device__ __forceinline__ void mma_16n8k8(float* d, const uint32_t* a, const uint32_t* b) {
    asm volatile(
        "mma.sync.aligned.m16n8k8.row.col.f32.tf32.tf32.f32 "
        "{%0,%1,%2,%3},{%4,%5,%6,%7},{%8,%9},{%0,%1,%2,%3};"
        : "+f"(d[0]), "+f"(d[1]), "+f"(d[2]), "+f"(d[3])
        : "r"(a[0]), "r"(a[1]), "r"(a[2]), "r"(a[3]), "r"(b[0]), "r"(b[1]));
}

// ================= router (fp64) =================
__global__ void router_kernel(const float* __restrict__ x,
                              const float* __restrict__ rw,
                              float* __restrict__ logits_out) {
    const int t = blockIdx.x;
    const int tid = threadIdx.x;
    const float* xr = x + (size_t)t * DDIM;
    double acc[NEXP];
#pragma unroll
    for (int e = 0; e < NEXP; e++) acc[e] = 0.0;
    const int k = tid * 4;
    float4 xv = *(const float4*)(xr + k);
#pragma unroll
    for (int e = 0; e < NEXP; e++) {
        float4 wv = *(const float4*)(rw + e * DDIM + k);
        acc[e] = fma((double)xv.x, (double)wv.x, acc[e]);
        acc[e] = fma((double)xv.y, (double)wv.y, acc[e]);
        acc[e] = fma((double)xv.z, (double)wv.z, acc[e]);
        acc[e] = fma((double)xv.w, (double)wv.w, acc[e]);
    }
#pragma unroll
    for (int e = 0; e < NEXP; e++)
#pragma unroll
        for (int o = 16; o; o >>= 1)
            acc[e] += __shfl_xor_sync(0xffffffffu, acc[e], o);
    __shared__ double red[NEXP][8];
    const int wid = tid >> 5, lid = tid & 31;
    if (lid == 0)
#pragma unroll
        for (int e = 0; e < NEXP; e++) red[e][wid] = acc[e];
    __syncthreads();
    if (tid == 0) {
        double l[NEXP], mx = -1e300;
#pragma unroll
        for (int e = 0; e < NEXP; e++) {
            double s = 0.0;
#pragma unroll
            for (int w = 0; w < 8; w++) s += red[e][w];
            l[e] = s; mx = fmax(mx, s);
        }
        double p[NEXP], sum = 0.0;
#pragma unroll
        for (int e = 0; e < NEXP; e++) { p[e] = exp(l[e] - mx); sum += p[e]; }
#pragma unroll
        for (int e = 0; e < NEXP; e++) {
            if (logits_out) logits_out[(size_t)t * NEXP + e] = (float)l[e];
            g_probs[(size_t)e * T_TOK + t] = p[e] / sum;
        }
    }
}

// ================= topk phase 1: sort 1024-chunks descending =================
__global__ void sort1024_kernel() {
    __shared__ unsigned long long key[1024];
    const int b = blockIdx.x;            // 64 blocks
    const int e = b >> 3, c = b & 7;
    const int tid = threadIdx.x;         // 512
#pragma unroll
    for (int q = 0; q < 2; q++) {
        const int i = tid + q * 512;
        const int gi = c * 1024 + i;
        double p = g_probs[(size_t)e * T_TOK + gi];
        unsigned long long db = __double_as_longlong(p);
        key[i] = (db & ~0x1FFFULL) | (unsigned long long)(8191 - gi);
    }
    __syncthreads();
    for (int k = 2; k <= 1024; k <<= 1) {
        for (int j = k >> 1; j > 0; j >>= 1) {
            const int i = ((tid & ~(j - 1)) << 1) | (tid & (j - 1));
            const int l = i | j;
            unsigned long long a = key[i], bb = key[l];
            bool descend = ((i & k) == 0);
            if ((a < bb) == descend) { key[i] = bb; key[l] = a; }
            __syncthreads();
        }
    }
    g_key0[(size_t)e * 8192 + c * 1024 + tid] = key[tid];
    g_key0[(size_t)e * 8192 + c * 1024 + tid + 512] = key[tid + 512];
}

// ================= topk phase 2: full merge tree per expert =================
__global__ void merge_tree_kernel(float* __restrict__ sel_out) {
    __shared__ unsigned long long buf[4][1024];
    __shared__ unsigned long long c[1024];
    const int e = blockIdx.x;
    const int tid = threadIdx.x;         // 512

    auto bitonic_desc = [&]() {
        for (int j = 512; j > 0; j >>= 1) {
            const int i = ((tid & ~(j - 1)) << 1) | (tid & (j - 1));
            const int l = i | j;
            unsigned long long x = c[i], y = c[l];
            if (x < y) { c[i] = y; c[l] = x; }
            __syncthreads();
        }
    };

#pragma unroll 1
    for (int p = 0; p < 4; p++) {
        const unsigned long long* A = g_key0 + (size_t)e * 8192 + (size_t)(2 * p) * 1024;
        const unsigned long long* B = A + 1024;
        unsigned long long a0 = A[tid], b0 = B[1023 - tid];
        c[tid] = a0 > b0 ? a0 : b0;
        unsigned long long a1 = A[tid + 512], b1 = B[511 - tid];
        c[tid + 512] = a1 > b1 ? a1 : b1;
        __syncthreads();
        bitonic_desc();
        buf[p][tid] = c[tid];
        buf[p][tid + 512] = c[tid + 512];
        __syncthreads();
    }
#pragma unroll 1
    for (int p = 0; p < 2; p++) {
        unsigned long long a0 = buf[2 * p][tid],       b0 = buf[2 * p + 1][1023 - tid];
        unsigned long long a1 = buf[2 * p][tid + 512], b1 = buf[2 * p + 1][511 - tid];
        c[tid] = a0 > b0 ? a0 : b0;
        c[tid + 512] = a1 > b1 ? a1 : b1;
        __syncthreads();
        bitonic_desc();
        buf[p][tid] = c[tid];
        buf[p][tid + 512] = c[tid + 512];
        __syncthreads();
    }
    {
        unsigned long long a0 = buf[0][tid],       b0 = buf[1][1023 - tid];
        unsigned long long a1 = buf[0][tid + 512], b1 = buf[1][511 - tid];
        c[tid] = a0 > b0 ? a0 : b0;
        c[tid + 512] = a1 > b1 ? a1 : b1;
        __syncthreads();
        bitonic_desc();
    }
#pragma unroll
    for (int q = 0; q < 2; q++) {
        const int i = tid + q * 512;
        unsigned long long kk = c[i];
        int idx = 8191 - (int)(kk & 0x1FFFULL);
        double val = __longlong_as_double((long long)(kk & ~0x1FFFULL));
        g_sel[e * KSEL + i] = idx;
        g_wts[e * KSEL + i] = (float)val;
        if (sel_out) sel_out[e * KSEL + i] = (float)idx;
    }
}

// ================= gather A rows -> packed layout + rna =================
__global__ void gather_x_kernel(const float* __restrict__ x) {
    const int row = blockIdx.x;                 // 0..8191
    const int e = row >> 10, i = row & 1023;
    const int tok = g_sel[e * KSEL + i];
    const int tid = threadIdx.x;                // 0..255
    float4 v = ((const float4*)(x + (size_t)tok * DDIM))[tid];
    v.x = tf32_rna(v.x); v.y = tf32_rna(v.y);
    v.z = tf32_rna(v.z); v.w = tf32_rna(v.w);
    const int kb = tid >> 1, h = tid & 1;
    const int rb = i >> 3, rr = i & 7;
    const size_t off = ((((size_t)e * 128 + kb) * 128 + rb) * 2 + h) * 32 + rr * 4;
    *(float4*)(g_xg + off) = v;
}

// ================= weight pack: [E][K][N] -> packed(r=n, k) + rna =================
__global__ void pack_w_kernel(const float* __restrict__ src, float* __restrict__ dst,
                              int K, int N) {
    __shared__ float t[32][33];
    const int e = blockIdx.z;
    const int k0 = blockIdx.y * 32, n0 = blockIdx.x * 32;
    const int tx = threadIdx.x, ty = threadIdx.y;
    const float* s = src + (size_t)e * K * N;
#pragma unroll
    for (int j = 0; j < 4; j++)
        t[ty + 8 * j][tx] = s[(size_t)(k0 + ty + 8 * j) * N + n0 + tx];
    __syncthreads();
    float4 v;
    v.x = tf32_rna(t[ty * 4 + 0][tx]);
    v.y = tf32_rna(t[ty * 4 + 1][tx]);
    v.z = tf32_rna(t[ty * 4 + 2][tx]);
    v.w = tf32_rna(t[ty * 4 + 3][tx]);
    const int n = n0 + tx, kv = k0 + ty * 4;
    const int kb = kv >> 3, h = (kv >> 2) & 1;
    const int nb = n >> 3, nn = n & 7;
    const size_t KB = (size_t)(K >> 3), NB = (size_t)(N >> 3);
    const size_t off = ((((size_t)e * KB + kb) * NB + nb) * 2 + h) * 32 + nn * 4;
    *(float4*)(dst + off) = v;
}

// ================= mma.m16n8k8 tf32 GEMM, CTA 128x128, warp 64x32 =================
// Register double-buffered ks-subtile fragments (hide LDSM latency behind MMAs).
#define BM   128
#define BN   128
#define LDC  132
#define STAGES 3

#define OFF_TOK   0                  // 128 ints
#define OFF_WT    512                // 128 floats
#define OFF_BIAS  1024               // 128 floats
#define OFF_DATA  2048
#define A_BYTES_S 16384
#define STAGE_SZ  32768
#define GEMM_SMEM (OFF_DATA + STAGES * STAGE_SZ)   // 100352

template <bool G1>
__global__ __launch_bounds__(256, 2)
void moe_mma_kernel(const float* __restrict__ Bw,     // packed weights
                    const float* __restrict__ bias,   // [E][N]
                    float* __restrict__ res) {
    extern __shared__ char smem[];
    const uint32_t sb = smem_u32(smem);
    const int tid = threadIdx.x;
    const int lane = tid & 31;
    const int e = blockIdx.z, by = blockIdx.y, bx = blockIdx.x;

    constexpr int KDIM = G1 ? DDIM : HDIM;
    constexpr int NTOT = G1 ? HDIM : DDIM;
    constexpr int KI = KDIM / 32;
    constexpr int RB = 128;
    constexpr int NB = NTOT / 8;

    const float* A = (G1 ? g_xg : g_h) + (size_t)e * KDIM * 1024;
    const float* B = Bw + (size_t)e * KDIM * NTOT;

    if (tid < 128) {
        ((float*)(smem + OFF_BIAS))[tid] = bias[e * NTOT + bx * BN + tid];
        if (!G1) {
            ((int*)(smem + OFF_TOK))[tid] = g_sel[e * KSEL + by * BM + tid];
            ((float*)(smem + OFF_WT))[tid] = g_wts[e * KSEL + by * BM + tid];
        }
    }

    auto load_stage = [&](int kt, int buf) {
        const uint32_t st = sb + OFF_DATA + buf * STAGE_SZ;
#pragma unroll
        for (int i = 0; i < 8; i++) {
            const int c = tid + 256 * i;         // 0..2047
            const int kb = (c >> 8) & 3, inner = c & 255;
            const float* src;
            if (c < 1024)
                src = A + ((size_t)(kt * 4 + kb) * RB + by * 16) * 64 + inner * 4;
            else
                src = B + ((size_t)(kt * 4 + kb) * NB + bx * 16) * 64 + inner * 4;
            cpasync16(st + c * 16, src);
        }
        asm volatile("cp.async.commit_group;" ::: "memory");
    };

    const int wid = tid >> 5;
    const int wm = wid & 1, wn = wid >> 1;
    const int msel = lane >> 3;
    const uint32_t aoff = (uint32_t)(((msel & 1) * 16 + (msel >> 1) * 8 + (lane & 7)));
    const uint32_t boff = (uint32_t)(((msel >> 1) * 16 + (msel & 1) * 8 + (lane & 7)));
    const uint32_t aWarp = (uint32_t)(wm * 8 * 16 + aoff) * 16;
    const uint32_t bWarp = (uint32_t)A_BYTES_S + ((uint32_t)(wn * 4 * 16 + boff) * 16);

    float acc[4][4][4];
#pragma unroll
    for (int i = 0; i < 4; i++)
#pragma unroll
        for (int j = 0; j < 4; j++)
#pragma unroll
            for (int q = 0; q < 4; q++) acc[i][j][q] = 0.f;

    // double-buffered fragment registers
    uint32_t afr[2][4][4], bfr[2][4][2];

    auto load_frags = [&](uint32_t ksb, int pb) {
#pragma unroll
        for (int mt = 0; mt < 4; mt++)
            ldsm_x4(afr[pb][mt], ksb + aWarp + mt * 512);
#pragma unroll
        for (int p = 0; p < 2; p++) {
            uint32_t r[4];
            ldsm_x4(r, ksb + bWarp + p * 512);
            bfr[pb][2 * p][0] = r[0]; bfr[pb][2 * p][1] = r[1];
            bfr[pb][2 * p + 1][0] = r[2]; bfr[pb][2 * p + 1][1] = r[3];
        }
    };

    load_stage(0, 0);
    load_stage(1, 1);

    int buf = 0;
#pragma unroll 1
    for (int kt = 0; kt < KI; kt++) {
        if (kt < KI - 1) asm volatile("cp.async.wait_group 1;" ::: "memory");
        else             asm volatile("cp.async.wait_group 0;" ::: "memory");
        __syncthreads();
        if (kt + 2 < KI) {
            int nb2 = buf + 2; if (nb2 >= STAGES) nb2 -= STAGES;
            load_stage(kt + 2, nb2);
        }
        const uint32_t st = sb + OFF_DATA + buf * STAGE_SZ;
        load_frags(st, 0);
#pragma unroll
        for (int ks = 0; ks < 4; ks++) {
            const int cur = ks & 1;
            if (ks < 3) load_frags(st + (ks + 1) * 4096, cur ^ 1);
#pragma unroll
            for (int mt = 0; mt < 4; mt++)
#pragma unroll
                for (int nt = 0; nt < 4; nt++)
                    mma_16n8k8(acc[mt][nt], afr[cur][mt], bfr[cur][nt]);
        }
        if (++buf == STAGES) buf = 0;
    }
    __syncthreads();

    // ---- stage C through smem ----
    float* Cs = (float*)(smem + OFF_DATA);
#pragma unroll
    for (int mt = 0; mt < 4; mt++)
#pragma unroll
        for (int nt = 0; nt < 4; nt++) {
            const int r0 = wm * 64 + mt * 16 + (lane >> 2);
            const int cc = wn * 32 + nt * 8 + (lane & 3) * 2;
            *(float2*)&Cs[r0 * LDC + cc]       = make_float2(acc[mt][nt][0], acc[mt][nt][1]);
            *(float2*)&Cs[(r0 + 8) * LDC + cc] = make_float2(acc[mt][nt][2], acc[mt][nt][3]);
        }
    __syncthreads();

    const float* sbias = (const float*)(smem + OFF_BIAS);
    if (G1) {
#pragma unroll
        for (int q = 0; q < 16; q++) {
            const int v = tid * 16 + q;
            const int r = v >> 5, c4 = (v & 31) * 4;
            float4 c = *(const float4*)(Cs + r * LDC + c4);
            c.x = tf32_rna(gelu_exact(c.x + sbias[c4 + 0]));
            c.y = tf32_rna(gelu_exact(c.y + sbias[c4 + 1]));
            c.z = tf32_rna(gelu_exact(c.z + sbias[c4 + 2]));
            c.w = tf32_rna(gelu_exact(c.w + sbias[c4 + 3]));
            const int n = bx * BN + c4;
            const int kb = n >> 3, h = (n >> 2) & 1;
            const int m = by * BM + r;
            const int rb = m >> 3, rr = m & 7;
            const size_t off = ((((size_t)e * 512 + kb) * 128 + rb) * 2 + h) * 32 + rr * 4;
            *(float4*)(g_h + off) = c;
        }
    } else {
        const int* tok = (const int*)(smem + OFF_TOK);
        const float* wts = (const float*)(smem + OFF_WT);
#pragma unroll
        for (int q = 0; q < 16; q++) {
            const int v = tid * 16 + q;
            const int r = v >> 5, c4 = (v & 31) * 4;
            float4 c = *(const float4*)(Cs + r * LDC + c4);
            const float g = wts[r];
            float* dst = res + (size_t)tok[r] * DDIM + bx * BN + c4;
            atomicAdd(dst + 0, (c.x + sbias[c4 + 0]) * g);
            atomicAdd(dst + 1, (c.y + sbias[c4 + 1]) * g);
            atomicAdd(dst + 2, (c.z + sbias[c4 + 2]) * g);
            atomicAdd(dst + 3, (c.w + sbias[c4 + 3]) * g);
        }
    }
}

// ================= launch =================
extern "C" void kernel_launch(void* const* d_in, const int* in_sizes, int n_in,
                              void* d_out, int out_size) {
    const float* x  = (const float*)d_in[0];
    const float* rw = (const float*)d_in[1];
    const float* w1 = (const float*)d_in[2];
    const float* b1 = (const float*)d_in[3];
    const float* w2 = (const float*)d_in[4];
    const float* b2 = (const float*)d_in[5];

    float* out = (float*)d_out;
    float* res = out;
    float* logits_out = nullptr;
    float* sel_out = nullptr;
    const long long TD = (long long)T_TOK * DDIM;
    if (out_size >= TD + T_TOK * NEXP) logits_out = out + TD;
    if (out_size >= TD + T_TOK * NEXP + NEXP * KSEL) sel_out = out + TD + T_TOK * NEXP;

    static cudaStream_t sw1 = nullptr, sw2 = nullptr;
    static cudaEvent_t ev0 = nullptr, ev1 = nullptr, ev2 = nullptr;
    if (!sw1) {
        cudaStreamCreateWithFlags(&sw1, cudaStreamNonBlocking);
        cudaStreamCreateWithFlags(&sw2, cudaStreamNonBlocking);
        cudaEventCreateWithFlags(&ev0, cudaEventDisableTiming);
        cudaEventCreateWithFlags(&ev1, cudaEventDisableTiming);
        cudaEventCreateWithFlags(&ev2, cudaEventDisableTiming);
    }

    float* w1r; cudaGetSymbolAddress((void**)&w1r, g_w1r);
    float* w2r; cudaGetSymbolAddress((void**)&w2r, g_w2r);

    cudaFuncSetAttribute(moe_mma_kernel<true>,
                         cudaFuncAttributeMaxDynamicSharedMemorySize, GEMM_SMEM);
    cudaFuncSetAttribute(moe_mma_kernel<false>,
                         cudaFuncAttributeMaxDynamicSharedMemorySize, GEMM_SMEM);

    // fork: weight packing + memset(res) on side streams
    cudaEventRecord(ev0, 0);
    cudaStreamWaitEvent(sw1, ev0, 0);
    cudaStreamWaitEvent(sw2, ev0, 0);
    pack_w_kernel<<<dim3(HDIM / 32, DDIM / 32, NEXP), dim3(32, 8), 0, sw1>>>(w1, w1r, DDIM, HDIM);
    cudaMemsetAsync(res, 0, (size_t)TD * sizeof(float), sw2);
    pack_w_kernel<<<dim3(DDIM / 32, HDIM / 32, NEXP), dim3(32, 8), 0, sw2>>>(w2, w2r, HDIM, DDIM);
    cudaEventRecord(ev1, sw1);
    cudaEventRecord(ev2, sw2);

    // main stream: router -> topk (sort + merge tree) -> gather
    router_kernel<<<T_TOK, 256>>>(x, rw, logits_out);
    sort1024_kernel<<<64, 512>>>();
    merge_tree_kernel<<<NEXP, 512>>>(sel_out);
    gather_x_kernel<<<NEXP * KSEL, 256>>>(x);

    // GEMM1 then GEMM2 (sequential; fused/k-split variants measured slower)
    cudaStreamWaitEvent(0, ev1, 0);
    moe_mma_kernel<true><<<dim3(HDIM / BN, KSEL / BM, NEXP), 256, GEMM_SMEM>>>(w1r, b1, nullptr);
    cudaStreamWaitEvent(0, ev2, 0);
    moe_mma_kernel<false><<<dim3(DDIM / BN, KSEL / BM, NEXP), 256, GEMM_SMEM>>>(w2r, b2, res);
}

// round 15
// speedup vs baseline: 1.0625x; 1.0196x over previous
#include <cuda_runtime.h>
#include <cuda_bf16.h>
#include <math.h>
#include <stdint.h>

// Problem constants
#define T_TOK   8192
#define DDIM    1024
#define HDIM    4096
#define NEXP    8
#define KSEL    1024

// ---------------- device scratch ----------------
// Packed operand layout (A and B of MMA):
//   element (row r, col k): kb=k>>3, rb=r>>3, h=(k>>2)&1, rr=r&7, kk=k&3
//   float offset = (((kb*RB + rb)*2 + h)*8 + rr)*4 + kk   (RB = rows/8)
__device__ double g_probs[NEXP * T_TOK];
__device__ int    g_sel[NEXP * KSEL];
__device__ float  g_wts[NEXP * KSEL];
__device__ float  g_xg [(size_t)NEXP * KSEL * DDIM];
__device__ float  g_h  [(size_t)NEXP * KSEL * HDIM];
__device__ float  g_w1r[(size_t)NEXP * DDIM * HDIM];
__device__ float  g_w2r[(size_t)NEXP * HDIM * DDIM];
__device__ unsigned long long g_key0[NEXP * 8192];

__device__ __forceinline__ uint32_t smem_u32(const void* p) {
    uint32_t a;
    asm("{ .reg .u64 t; cvta.to.shared.u64 t, %1; cvt.u32.u64 %0, t; }" : "=r"(a) : "l"(p));
    return a;
}
__device__ __forceinline__ void cpasync16(uint32_t dst, const void* src) {
    asm volatile("cp.async.cg.shared.global [%0], [%1], 16;" :: "r"(dst), "l"(src) : "memory");
}
__device__ __forceinline__ float tf32_rna(float v) {
    uint32_t o;
    asm("cvt.rna.tf32.f32 %0, %1;" : "=r"(o) : "f"(v));
    return __uint_as_float(o);
}
__device__ __forceinline__ float gelu_exact(float v) {
    return 0.5f * v * (1.0f + erff(v * 0.7071067811865476f));
}
__device__ __forceinline__ void ldsm_x4(uint32_t* r, uint32_t addr) {
    asm volatile("ldmatrix.sync.aligned.m8n8.x4.shared.b16 {%0,%1,%2,%3}, [%4];"
                 : "=r"(r[0]), "=r"(r[1]), "=r"(r[2]), "=r"(r[3]) : "r"(addr));
}
__device__ __forceinline__ void mma_16n8k8(float* d, const uint32_t* a, const uint32_t* b) {
    asm volatile(
        "mma.sync.aligned.m16n8k8.row.col.f32.tf32.tf32.f32 "
        "{%0,%1,%2,%3},{%4,%5,%6,%7},{%8,%9},{%0,%1,%2,%3};"
        : "+f"(d[0]), "+f"(d[1]), "+f"(d[2]), "+f"(d[3])
        : "r"(a[0]), "r"(a[1]), "r"(a[2]), "r"(a[3]), "r"(b[0]), "r"(b[1]));
}
__device__ __forceinline__ void red_add_v4(float* p, float a, float b, float c, float d) {
    asm volatile("red.global.add.v4.f32 [%0], {%1,%2,%3,%4};"
                 :: "l"(p), "f"(a), "f"(b), "f"(c), "f"(d) : "memory");
}

// ================= router (fp64) =================
__global__ void router_kernel(const float* __restrict__ x,
                              const float* __restrict__ rw,
                              float* __restrict__ logits_out) {
    const int t = blockIdx.x;
    const int tid = threadIdx.x;
    const float* xr = x + (size_t)t * DDIM;
    double acc[NEXP];
#pragma unroll
    for (int e = 0; e < NEXP; e++) acc[e] = 0.0;
    const int k = tid * 4;
    float4 xv = *(const float4*)(xr + k);
#pragma unroll
    for (int e = 0; e < NEXP; e++) {
        float4 wv = *(const float4*)(rw + e * DDIM + k);
        acc[e] = fma((double)xv.x, (double)wv.x, acc[e]);
        acc[e] = fma((double)xv.y, (double)wv.y, acc[e]);
        acc[e] = fma((double)xv.z, (double)wv.z, acc[e]);
        acc[e] = fma((double)xv.w, (double)wv.w, acc[e]);
    }
#pragma unroll
    for (int e = 0; e < NEXP; e++)
#pragma unroll
        for (int o = 16; o; o >>= 1)
            acc[e] += __shfl_xor_sync(0xffffffffu, acc[e], o);
    __shared__ double red[NEXP][8];
    const int wid = tid >> 5, lid = tid & 31;
    if (lid == 0)
#pragma unroll
        for (int e = 0; e < NEXP; e++) red[e][wid] = acc[e];
    __syncthreads();
    if (tid == 0) {
        double l[NEXP], mx = -1e300;
#pragma unroll
        for (int e = 0; e < NEXP; e++) {
            double s = 0.0;
#pragma unroll
            for (int w = 0; w < 8; w++) s += red[e][w];
            l[e] = s; mx = fmax(mx, s);
        }
        double p[NEXP], sum = 0.0;
#pragma unroll
        for (int e = 0; e < NEXP; e++) { p[e] = exp(l[e] - mx); sum += p[e]; }
#pragma unroll
        for (int e = 0; e < NEXP; e++) {
            if (logits_out) logits_out[(size_t)t * NEXP + e] = (float)l[e];
            g_probs[(size_t)e * T_TOK + t] = p[e] / sum;
        }
    }
}

// ================= topk phase 1: sort 1024-chunks descending =================
__global__ void sort1024_kernel() {
    __shared__ unsigned long long key[1024];
    const int b = blockIdx.x;            // 64 blocks
    const int e = b >> 3, c = b & 7;
    const int tid = threadIdx.x;         // 512
#pragma unroll
    for (int q = 0; q < 2; q++) {
        const int i = tid + q * 512;
        const int gi = c * 1024 + i;
        double p = g_probs[(size_t)e * T_TOK + gi];
        unsigned long long db = __double_as_longlong(p);
        key[i] = (db & ~0x1FFFULL) | (unsigned long long)(8191 - gi);
    }
    __syncthreads();
    for (int k = 2; k <= 1024; k <<= 1) {
        for (int j = k >> 1; j > 0; j >>= 1) {
            const int i = ((tid & ~(j - 1)) << 1) | (tid & (j - 1));
            const int l = i | j;
            unsigned long long a = key[i], bb = key[l];
            bool descend = ((i & k) == 0);
            if ((a < bb) == descend) { key[i] = bb; key[l] = a; }
            __syncthreads();
        }
    }
    g_key0[(size_t)e * 8192 + c * 1024 + tid] = key[tid];
    g_key0[(size_t)e * 8192 + c * 1024 + tid + 512] = key[tid + 512];
}

// ================= topk phase 2: full merge tree per expert =================
__global__ void merge_tree_kernel(float* __restrict__ sel_out) {
    __shared__ unsigned long long buf[4][1024];
    __shared__ unsigned long long c[1024];
    const int e = blockIdx.x;
    const int tid = threadIdx.x;         // 512

    auto bitonic_desc = [&]() {
        for (int j = 512; j > 0; j >>= 1) {
            const int i = ((tid & ~(j - 1)) << 1) | (tid & (j - 1));
            const int l = i | j;
            unsigned long long x = c[i], y = c[l];
            if (x < y) { c[i] = y; c[l] = x; }
            __syncthreads();
        }
    };

#pragma unroll 1
    for (int p = 0; p < 4; p++) {
        const unsigned long long* A = g_key0 + (size_t)e * 8192 + (size_t)(2 * p) * 1024;
        const unsigned long long* B = A + 1024;
        unsigned long long a0 = A[tid], b0 = B[1023 - tid];
        c[tid] = a0 > b0 ? a0 : b0;
        unsigned long long a1 = A[tid + 512], b1 = B[511 - tid];
        c[tid + 512] = a1 > b1 ? a1 : b1;
        __syncthreads();
        bitonic_desc();
        buf[p][tid] = c[tid];
        buf[p][tid + 512] = c[tid + 512];
        __syncthreads();
    }
#pragma unroll 1
    for (int p = 0; p < 2; p++) {
        unsigned long long a0 = buf[2 * p][tid],       b0 = buf[2 * p + 1][1023 - tid];
        unsigned long long a1 = buf[2 * p][tid + 512], b1 = buf[2 * p + 1][511 - tid];
        c[tid] = a0 > b0 ? a0 : b0;
        c[tid + 512] = a1 > b1 ? a1 : b1;
        __syncthreads();
        bitonic_desc();
        buf[p][tid] = c[tid];
        buf[p][tid + 512] = c[tid + 512];
        __syncthreads();
    }
    {
        unsigned long long a0 = buf[0][tid],       b0 = buf[1][1023 - tid];
        unsigned long long a1 = buf[0][tid + 512], b1 = buf[1][511 - tid];
        c[tid] = a0 > b0 ? a0 : b0;
        c[tid + 512] = a1 > b1 ? a1 : b1;
        __syncthreads();
        bitonic_desc();
    }
#pragma unroll
    for (int q = 0; q < 2; q++) {
        const int i = tid + q * 512;
        unsigned long long kk = c[i];
        int idx = 8191 - (int)(kk & 0x1FFFULL);
        double val = __longlong_as_double((long long)(kk & ~0x1FFFULL));
        g_sel[e * KSEL + i] = idx;
        g_wts[e * KSEL + i] = (float)val;
        if (sel_out) sel_out[e * KSEL + i] = (float)idx;
    }
}

// ================= gather A rows -> packed layout + rna =================
__global__ void gather_x_kernel(const float* __restrict__ x) {
    const int row = blockIdx.x;                 // 0..8191
    const int e = row >> 10, i = row & 1023;
    const int tok = g_sel[e * KSEL + i];
    const int tid = threadIdx.x;                // 0..255
    float4 v = ((const float4*)(x + (size_t)tok * DDIM))[tid];
    v.x = tf32_rna(v.x); v.y = tf32_rna(v.y);
    v.z = tf32_rna(v.z); v.w = tf32_rna(v.w);
    const int kb = tid >> 1, h = tid & 1;
    const int rb = i >> 3, rr = i & 7;
    const size_t off = ((((size_t)e * 128 + kb) * 128 + rb) * 2 + h) * 32 + rr * 4;
    *(float4*)(g_xg + off) = v;
}

// ================= weight pack: [E][K][N] -> packed(r=n, k) + rna =================
__global__ void pack_w_kernel(const float* __restrict__ src, float* __restrict__ dst,
                              int K, int N) {
    __shared__ float t[32][33];
    const int e = blockIdx.z;
    const int k0 = blockIdx.y * 32, n0 = blockIdx.x * 32;
    const int tx = threadIdx.x, ty = threadIdx.y;
    const float* s = src + (size_t)e * K * N;
#pragma unroll
    for (int j = 0; j < 4; j++)
        t[ty + 8 * j][tx] = s[(size_t)(k0 + ty + 8 * j) * N + n0 + tx];
    __syncthreads();
    float4 v;
    v.x = tf32_rna(t[ty * 4 + 0][tx]);
    v.y = tf32_rna(t[ty * 4 + 1][tx]);
    v.z = tf32_rna(t[ty * 4 + 2][tx]);
    v.w = tf32_rna(t[ty * 4 + 3][tx]);
    const int n = n0 + tx, kv = k0 + ty * 4;
    const int kb = kv >> 3, h = (kv >> 2) & 1;
    const int nb = n >> 3, nn = n & 7;
    const size_t KB = (size_t)(K >> 3), NB = (size_t)(N >> 3);
    const size_t off = ((((size_t)e * KB + kb) * NB + nb) * 2 + h) * 32 + nn * 4;
    *(float4*)(dst + off) = v;
}

// ================= mma.m16n8k8 tf32 GEMM, CTA 128x128, warp 64x32 =================
// Register double-buffered ks-subtile fragments (hide LDSM latency behind MMAs).
#define BM   128
#define BN   128
#define LDC  132
#define STAGES 3

#define OFF_TOK   0                  // 128 ints
#define OFF_WT    512                // 128 floats
#define OFF_BIAS  1024               // 128 floats
#define OFF_DATA  2048
#define A_BYTES_S 16384
#define STAGE_SZ  32768
#define GEMM_SMEM (OFF_DATA + STAGES * STAGE_SZ)   // 100352

template <bool G1>
__global__ __launch_bounds__(256, 2)
void moe_mma_kernel(const float* __restrict__ Bw,     // packed weights
                    const float* __restrict__ bias,   // [E][N]
                    float* __restrict__ res) {
    extern __shared__ char smem[];
    const uint32_t sb = smem_u32(smem);
    const int tid = threadIdx.x;
    const int lane = tid & 31;
    const int e = blockIdx.z, by = blockIdx.y, bx = blockIdx.x;

    constexpr int KDIM = G1 ? DDIM : HDIM;
    constexpr int NTOT = G1 ? HDIM : DDIM;
    constexpr int KI = KDIM / 32;
    constexpr int RB = 128;
    constexpr int NB = NTOT / 8;

    const float* A = (G1 ? g_xg : g_h) + (size_t)e * KDIM * 1024;
    const float* B = Bw + (size_t)e * KDIM * NTOT;

    if (tid < 128) {
        ((float*)(smem + OFF_BIAS))[tid] = bias[e * NTOT + bx * BN + tid];
        if (!G1) {
            ((int*)(smem + OFF_TOK))[tid] = g_sel[e * KSEL + by * BM + tid];
            ((float*)(smem + OFF_WT))[tid] = g_wts[e * KSEL + by * BM + tid];
        }
    }

    auto load_stage = [&](int kt, int buf) {
        const uint32_t st = sb + OFF_DATA + buf * STAGE_SZ;
#pragma unroll
        for (int i = 0; i < 8; i++) {
            const int c = tid + 256 * i;         // 0..2047
            const int kb = (c >> 8) & 3, inner = c & 255;
            const float* src;
            if (c < 1024)
                src = A + ((size_t)(kt * 4 + kb) * RB + by * 16) * 64 + inner * 4;
            else
                src = B + ((size_t)(kt * 4 + kb) * NB + bx * 16) * 64 + inner * 4;
            cpasync16(st + c * 16, src);
        }
        asm volatile("cp.async.commit_group;" ::: "memory");
    };

    const int wid = tid >> 5;
    const int wm = wid & 1, wn = wid >> 1;
    const int msel = lane >> 3;
    const uint32_t aoff = (uint32_t)(((msel & 1) * 16 + (msel >> 1) * 8 + (lane & 7)));
    const uint32_t boff = (uint32_t)(((msel >> 1) * 16 + (msel & 1) * 8 + (lane & 7)));
    const uint32_t aWarp = (uint32_t)(wm * 8 * 16 + aoff) * 16;
    const uint32_t bWarp = (uint32_t)A_BYTES_S + ((uint32_t)(wn * 4 * 16 + boff) * 16);

    float acc[4][4][4];
#pragma unroll
    for (int i = 0; i < 4; i++)
#pragma unroll
        for (int j = 0; j < 4; j++)
#pragma unroll
            for (int q = 0; q < 4; q++) acc[i][j][q] = 0.f;

    // double-buffered fragment registers
    uint32_t afr[2][4][4], bfr[2][4][2];

    auto load_frags = [&](uint32_t ksb, int pb) {
#pragma unroll
        for (int mt = 0; mt < 4; mt++)
            ldsm_x4(afr[pb][mt], ksb + aWarp + mt * 512);
#pragma unroll
        for (int p = 0; p < 2; p++) {
            uint32_t r[4];
            ldsm_x4(r, ksb + bWarp + p * 512);
            bfr[pb][2 * p][0] = r[0]; bfr[pb][2 * p][1] = r[1];
            bfr[pb][2 * p + 1][0] = r[2]; bfr[pb][2 * p + 1][1] = r[3];
        }
    };

    load_stage(0, 0);
    load_stage(1, 1);

    int buf = 0;
#pragma unroll 1
    for (int kt = 0; kt < KI; kt++) {
        if (kt < KI - 1) asm volatile("cp.async.wait_group 1;" ::: "memory");
        else             asm volatile("cp.async.wait_group 0;" ::: "memory");
        __syncthreads();
        if (kt + 2 < KI) {
            int nb2 = buf + 2; if (nb2 >= STAGES) nb2 -= STAGES;
            load_stage(kt + 2, nb2);
        }
        const uint32_t st = sb + OFF_DATA + buf * STAGE_SZ;
        load_frags(st, 0);
#pragma unroll
        for (int ks = 0; ks < 4; ks++) {
            const int cur = ks & 1;
            if (ks < 3) load_frags(st + (ks + 1) * 4096, cur ^ 1);
#pragma unroll
            for (int mt = 0; mt < 4; mt++)
#pragma unroll
                for (int nt = 0; nt < 4; nt++)
                    mma_16n8k8(acc[mt][nt], afr[cur][mt], bfr[cur][nt]);
        }
        if (++buf == STAGES) buf = 0;
    }
    __syncthreads();

    // ---- stage C through smem ----
    float* Cs = (float*)(smem + OFF_DATA);
#pragma unroll
    for (int mt = 0; mt < 4; mt++)
#pragma unroll
        for (int nt = 0; nt < 4; nt++) {
            const int r0 = wm * 64 + mt * 16 + (lane >> 2);
            const int cc = wn * 32 + nt * 8 + (lane & 3) * 2;
            *(float2*)&Cs[r0 * LDC + cc]       = make_float2(acc[mt][nt][0], acc[mt][nt][1]);
            *(float2*)&Cs[(r0 + 8) * LDC + cc] = make_float2(acc[mt][nt][2], acc[mt][nt][3]);
        }
    __syncthreads();

    const float* sbias = (const float*)(smem + OFF_BIAS);
    if (G1) {
#pragma unroll
        for (int q = 0; q < 16; q++) {
            const int v = tid * 16 + q;
            const int r = v >> 5, c4 = (v & 31) * 4;
            float4 c = *(const float4*)(Cs + r * LDC + c4);
            c.x = tf32_rna(gelu_exact(c.x + sbias[c4 + 0]));
            c.y = tf32_rna(gelu_exact(c.y + sbias[c4 + 1]));
            c.z = tf32_rna(gelu_exact(c.z + sbias[c4 + 2]));
            c.w = tf32_rna(gelu_exact(c.w + sbias[c4 + 3]));
            const int n = bx * BN + c4;
            const int kb = n >> 3, h = (n >> 2) & 1;
            const int m = by * BM + r;
            const int rb = m >> 3, rr = m & 7;
            const size_t off = ((((size_t)e * 512 + kb) * 128 + rb) * 2 + h) * 32 + rr * 4;
            *(float4*)(g_h + off) = c;
        }
    } else {
        const int* tok = (const int*)(smem + OFF_TOK);
        const float* wts = (const float*)(smem + OFF_WT);
#pragma unroll
        for (int q = 0; q < 16; q++) {
            const int v = tid * 16 + q;
            const int r = v >> 5, c4 = (v & 31) * 4;
            float4 c = *(const float4*)(Cs + r * LDC + c4);
            const float g = wts[r];
            float* dst = res + (size_t)tok[r] * DDIM + bx * BN + c4;
            red_add_v4(dst,
                       (c.x + sbias[c4 + 0]) * g,
                       (c.y + sbias[c4 + 1]) * g,
                       (c.z + sbias[c4 + 2]) * g,
                       (c.w + sbias[c4 + 3]) * g);
        }
    }
}

// ================= launch =================
extern "C" void kernel_launch(void* const* d_in, const int* in_sizes, int n_in,
                              void* d_out, int out_size) {
    const float* x  = (const float*)d_in[0];
    const float* rw = (const float*)d_in[1];
    const float* w1 = (const float*)d_in[2];
    const float* b1 = (const float*)d_in[3];
    const float* w2 = (const float*)d_in[4];
    const float* b2 = (const float*)d_in[5];

    float* out = (float*)d_out;
    float* res = out;
    float* logits_out = nullptr;
    float* sel_out = nullptr;
    const long long TD = (long long)T_TOK * DDIM;
    if (out_size >= TD + T_TOK * NEXP) logits_out = out + TD;
    if (out_size >= TD + T_TOK * NEXP + NEXP * KSEL) sel_out = out + TD + T_TOK * NEXP;

    static cudaStream_t sw1 = nullptr, sw2 = nullptr;
    static cudaEvent_t ev0 = nullptr, ev1 = nullptr, ev2 = nullptr, ev3 = nullptr;
    if (!sw1) {
        cudaStreamCreateWithFlags(&sw1, cudaStreamNonBlocking);
        cudaStreamCreateWithFlags(&sw2, cudaStreamNonBlocking);
        cudaEventCreateWithFlags(&ev0, cudaEventDisableTiming);
        cudaEventCreateWithFlags(&ev1, cudaEventDisableTiming);
        cudaEventCreateWithFlags(&ev2, cudaEventDisableTiming);
        cudaEventCreateWithFlags(&ev3, cudaEventDisableTiming);
    }

    float* w1r; cudaGetSymbolAddress((void**)&w1r, g_w1r);
    float* w2r; cudaGetSymbolAddress((void**)&w2r, g_w2r);

    cudaFuncSetAttribute(moe_mma_kernel<true>,
                         cudaFuncAttributeMaxDynamicSharedMemorySize, GEMM_SMEM);
    cudaFuncSetAttribute(moe_mma_kernel<false>,
                         cudaFuncAttributeMaxDynamicSharedMemorySize, GEMM_SMEM);

    // fork: pack_w1 -> pack_w2 serialized on sw1 (pack_w1 gets full bandwidth
    // so GEMM1's gate clears inside the router/topk shadow); memset(res) on sw2.
    cudaEventRecord(ev0, 0);
    cudaStreamWaitEvent(sw1, ev0, 0);
    cudaStreamWaitEvent(sw2, ev0, 0);
    pack_w_kernel<<<dim3(HDIM / 32, DDIM / 32, NEXP), dim3(32, 8), 0, sw1>>>(w1, w1r, DDIM, HDIM);
    cudaEventRecord(ev1, sw1);                 // w1r ready
    pack_w_kernel<<<dim3(DDIM / 32, HDIM / 32, NEXP), dim3(32, 8), 0, sw1>>>(w2, w2r, HDIM, DDIM);
    cudaEventRecord(ev2, sw1);                 // w2r ready
    cudaMemsetAsync(res, 0, (size_t)TD * sizeof(float), sw2);
    cudaEventRecord(ev3, sw2);                 // res zeroed

    // main stream: router -> topk (sort + merge tree) -> gather
    router_kernel<<<T_TOK, 256>>>(x, rw, logits_out);
    sort1024_kernel<<<64, 512>>>();
    merge_tree_kernel<<<NEXP, 512>>>(sel_out);
    gather_x_kernel<<<NEXP * KSEL, 256>>>(x);

    // GEMM1 then GEMM2
    cudaStreamWaitEvent(0, ev1, 0);
    moe_mma_kernel<true><<<dim3(HDIM / BN, KSEL / BM, NEXP), 256, GEMM_SMEM>>>(w1r, b1, nullptr);
    cudaStreamWaitEvent(0, ev2, 0);
    cudaStreamWaitEvent(0, ev3, 0);
    moe_mma_kernel<false><<<dim3(DDIM / BN, KSEL / BM, NEXP), 256, GEMM_SMEM>>>(w2r, b2, res);
}

// round 16
// speedup vs baseline: 1.0716x; 1.0086x over previous
#include <cuda_runtime.h>
#include <cuda_bf16.h>
#include <math.h>
#include <stdint.h>

// Problem constants
#define T_TOK   8192
#define DDIM    1024
#define HDIM    4096
#define NEXP    8
#define KSEL    1024

// ---------------- device scratch ----------------
// Packed operand layout (A and B of MMA):
//   element (row r, col k): kb=k>>3, rb=r>>3, h=(k>>2)&1, rr=r&7, kk=k&3
//   float offset = (((kb*RB + rb)*2 + h)*8 + rr)*4 + kk   (RB = rows/8)
__device__ double g_probs[NEXP * T_TOK];
__device__ int    g_sel[NEXP * KSEL];
__device__ float  g_wts[NEXP * KSEL];
__device__ float  g_xg [(size_t)NEXP * KSEL * DDIM];
__device__ float  g_h  [(size_t)NEXP * KSEL * HDIM];
__device__ float  g_w1r[(size_t)NEXP * DDIM * HDIM];
__device__ float  g_w2r[(size_t)NEXP * HDIM * DDIM];
__device__ unsigned long long g_key0[NEXP * 8192];

__device__ __forceinline__ uint32_t smem_u32(const void* p) {
    uint32_t a;
    asm("{ .reg .u64 t; cvta.to.shared.u64 t, %1; cvt.u32.u64 %0, t; }" : "=r"(a) : "l"(p));
    return a;
}
__device__ __forceinline__ void cpasync16(uint32_t dst, const void* src) {
    asm volatile("cp.async.cg.shared.global [%0], [%1], 16;" :: "r"(dst), "l"(src) : "memory");
}
__device__ __forceinline__ float tf32_rna(float v) {
    uint32_t o;
    asm("cvt.rna.tf32.f32 %0, %1;" : "=r"(o) : "f"(v));
    return __uint_as_float(o);
}
__device__ __forceinline__ float gelu_exact(float v) {
    return 0.5f * v * (1.0f + erff(v * 0.7071067811865476f));
}
__device__ __forceinline__ void ldsm_x4(uint32_t* r, uint32_t addr) {
    asm volatile("ldmatrix.sync.aligned.m8n8.x4.shared.b16 {%0,%1,%2,%3}, [%4];"
                 : "=r"(r[0]), "=r"(r[1]), "=r"(r[2]), "=r"(r[3]) : "r"(addr));
}
__device__ __forceinline__ void mma_16n8k8(float* d, const uint32_t* a, const uint32_t* b) {
    asm volatile(
        "mma.sync.aligned.m16n8k8.row.col.f32.tf32.tf32.f32 "
        "{%0,%1,%2,%3},{%4,%5,%6,%7},{%8,%9},{%0,%1,%2,%3};"
        : "+f"(d[0]), "+f"(d[1]), "+f"(d[2]), "+f"(d[3])
        : "r"(a[0]), "r"(a[1]), "r"(a[2]), "r"(a[3]), "r"(b[0]), "r"(b[1]));
}
__device__ __forceinline__ void red_add_v4(float* p, float a, float b, float c, float d) {
    asm volatile("red.global.add.v4.f32 [%0], {%1,%2,%3,%4};"
                 :: "l"(p), "f"(a), "f"(b), "f"(c), "f"(d) : "memory");
}

// ================= router (fp64) =================
__global__ void router_kernel(const float* __restrict__ x,
                              const float* __restrict__ rw,
                              float* __restrict__ logits_out) {
    const int t = blockIdx.x;
    const int tid = threadIdx.x;
    const float* xr = x + (size_t)t * DDIM;
    double acc[NEXP];
#pragma unroll
    for (int e = 0; e < NEXP; e++) acc[e] = 0.0;
    const int k = tid * 4;
    float4 xv = *(const float4*)(xr + k);
#pragma unroll
    for (int e = 0; e < NEXP; e++) {
        float4 wv = *(const float4*)(rw + e * DDIM + k);
        acc[e] = fma((double)xv.x, (double)wv.x, acc[e]);
        acc[e] = fma((double)xv.y, (double)wv.y, acc[e]);
        acc[e] = fma((double)xv.z, (double)wv.z, acc[e]);
        acc[e] = fma((double)xv.w, (double)wv.w, acc[e]);
    }
#pragma unroll
    for (int e = 0; e < NEXP; e++)
#pragma unroll
        for (int o = 16; o; o >>= 1)
            acc[e] += __shfl_xor_sync(0xffffffffu, acc[e], o);
    __shared__ double red[NEXP][8];
    const int wid = tid >> 5, lid = tid & 31;
    if (lid == 0)
#pragma unroll
        for (int e = 0; e < NEXP; e++) red[e][wid] = acc[e];
    __syncthreads();
    if (tid == 0) {
        double l[NEXP], mx = -1e300;
#pragma unroll
        for (int e = 0; e < NEXP; e++) {
            double s = 0.0;
#pragma unroll
            for (int w = 0; w < 8; w++) s += red[e][w];
            l[e] = s; mx = fmax(mx, s);
        }
        double p[NEXP], sum = 0.0;
#pragma unroll
        for (int e = 0; e < NEXP; e++) { p[e] = exp(l[e] - mx); sum += p[e]; }
#pragma unroll
        for (int e = 0; e < NEXP; e++) {
            if (logits_out) logits_out[(size_t)t * NEXP + e] = (float)l[e];
            g_probs[(size_t)e * T_TOK + t] = p[e] / sum;
        }
    }
}

// ================= topk phase 1: sort 1024-chunks descending =================
__global__ void sort1024_kernel() {
    __shared__ unsigned long long key[1024];
    const int b = blockIdx.x;            // 64 blocks
    const int e = b >> 3, c = b & 7;
    const int tid = threadIdx.x;         // 512
#pragma unroll
    for (int q = 0; q < 2; q++) {
        const int i = tid + q * 512;
        const int gi = c * 1024 + i;
        double p = g_probs[(size_t)e * T_TOK + gi];
        unsigned long long db = __double_as_longlong(p);
        key[i] = (db & ~0x1FFFULL) | (unsigned long long)(8191 - gi);
    }
    __syncthreads();
    for (int k = 2; k <= 1024; k <<= 1) {
        for (int j = k >> 1; j > 0; j >>= 1) {
            const int i = ((tid & ~(j - 1)) << 1) | (tid & (j - 1));
            const int l = i | j;
            unsigned long long a = key[i], bb = key[l];
            bool descend = ((i & k) == 0);
            if ((a < bb) == descend) { key[i] = bb; key[l] = a; }
            __syncthreads();
        }
    }
    g_key0[(size_t)e * 8192 + c * 1024 + tid] = key[tid];
    g_key0[(size_t)e * 8192 + c * 1024 + tid + 512] = key[tid + 512];
}

// ================= topk phase 2: full merge tree per expert =================
__global__ void merge_tree_kernel(float* __restrict__ sel_out) {
    __shared__ unsigned long long buf[4][1024];
    __shared__ unsigned long long c[1024];
    const int e = blockIdx.x;
    const int tid = threadIdx.x;         // 512

    auto bitonic_desc = [&]() {
        for (int j = 512; j > 0; j >>= 1) {
            const int i = ((tid & ~(j - 1)) << 1) | (tid & (j - 1));
            const int l = i | j;
            unsigned long long x = c[i], y = c[l];
            if (x < y) { c[i] = y; c[l] = x; }
            __syncthreads();
        }
    };

#pragma unroll 1
    for (int p = 0; p < 4; p++) {
        const unsigned long long* A = g_key0 + (size_t)e * 8192 + (size_t)(2 * p) * 1024;
        const unsigned long long* B = A + 1024;
        unsigned long long a0 = A[tid], b0 = B[1023 - tid];
        c[tid] = a0 > b0 ? a0 : b0;
        unsigned long long a1 = A[tid + 512], b1 = B[511 - tid];
        c[tid + 512] = a1 > b1 ? a1 : b1;
        __syncthreads();
        bitonic_desc();
        buf[p][tid] = c[tid];
        buf[p][tid + 512] = c[tid + 512];
        __syncthreads();
    }
#pragma unroll 1
    for (int p = 0; p < 2; p++) {
        unsigned long long a0 = buf[2 * p][tid],       b0 = buf[2 * p + 1][1023 - tid];
        unsigned long long a1 = buf[2 * p][tid + 512], b1 = buf[2 * p + 1][511 - tid];
        c[tid] = a0 > b0 ? a0 : b0;
        c[tid + 512] = a1 > b1 ? a1 : b1;
        __syncthreads();
        bitonic_desc();
        buf[p][tid] = c[tid];
        buf[p][tid + 512] = c[tid + 512];
        __syncthreads();
    }
    {
        unsigned long long a0 = buf[0][tid],       b0 = buf[1][1023 - tid];
        unsigned long long a1 = buf[0][tid + 512], b1 = buf[1][511 - tid];
        c[tid] = a0 > b0 ? a0 : b0;
        c[tid + 512] = a1 > b1 ? a1 : b1;
        __syncthreads();
        bitonic_desc();
    }
#pragma unroll
    for (int q = 0; q < 2; q++) {
        const int i = tid + q * 512;
        unsigned long long kk = c[i];
        int idx = 8191 - (int)(kk & 0x1FFFULL);
        double val = __longlong_as_double((long long)(kk & ~0x1FFFULL));
        g_sel[e * KSEL + i] = idx;
        g_wts[e * KSEL + i] = (float)val;
        if (sel_out) sel_out[e * KSEL + i] = (float)idx;
    }
}

// ================= gather A rows -> packed layout + rna =================
__global__ void gather_x_kernel(const float* __restrict__ x) {
    const int row = blockIdx.x;                 // 0..8191
    const int e = row >> 10, i = row & 1023;
    const int tok = g_sel[e * KSEL + i];
    const int tid = threadIdx.x;                // 0..255
    float4 v = ((const float4*)(x + (size_t)tok * DDIM))[tid];
    v.x = tf32_rna(v.x); v.y = tf32_rna(v.y);
    v.z = tf32_rna(v.z); v.w = tf32_rna(v.w);
    const int kb = tid >> 1, h = tid & 1;
    const int rb = i >> 3, rr = i & 7;
    const size_t off = ((((size_t)e * 128 + kb) * 128 + rb) * 2 + h) * 32 + rr * 4;
    *(float4*)(g_xg + off) = v;
}

// ================= weight pack: [E][K][N] -> packed(r=n, k) + rna =================
__global__ void pack_w_kernel(const float* __restrict__ src, float* __restrict__ dst,
                              int K, int N) {
    __shared__ float t[32][33];
    const int e = blockIdx.z;
    const int k0 = blockIdx.y * 32, n0 = blockIdx.x * 32;
    const int tx = threadIdx.x, ty = threadIdx.y;
    const float* s = src + (size_t)e * K * N;
#pragma unroll
    for (int j = 0; j < 4; j++)
        t[ty + 8 * j][tx] = s[(size_t)(k0 + ty + 8 * j) * N + n0 + tx];
    __syncthreads();
    float4 v;
    v.x = tf32_rna(t[ty * 4 + 0][tx]);
    v.y = tf32_rna(t[ty * 4 + 1][tx]);
    v.z = tf32_rna(t[ty * 4 + 2][tx]);
    v.w = tf32_rna(t[ty * 4 + 3][tx]);
    const int n = n0 + tx, kv = k0 + ty * 4;
    const int kb = kv >> 3, h = (kv >> 2) & 1;
    const int nb = n >> 3, nn = n & 7;
    const size_t KB = (size_t)(K >> 3), NB = (size_t)(N >> 3);
    const size_t off = ((((size_t)e * KB + kb) * NB + nb) * 2 + h) * 32 + nn * 4;
    *(float4*)(dst + off) = v;
}

// ================= mma.m16n8k8 tf32 GEMM, CTA 128x128, warp 64x32 =================
// Register double-buffered ks-subtile fragments; GEMM1 epilogue stores C
// directly to the packed g_h layout (no smem staging, no extra barriers).
#define BM   128
#define BN   128
#define LDC  132
#define STAGES 3

#define OFF_TOK   0                  // 128 ints
#define OFF_WT    512                // 128 floats
#define OFF_BIAS  1024               // 128 floats
#define OFF_DATA  2048
#define A_BYTES_S 16384
#define STAGE_SZ  32768
#define GEMM_SMEM (OFF_DATA + STAGES * STAGE_SZ)   // 100352

template <bool G1>
__global__ __launch_bounds__(256, 2)
void moe_mma_kernel(const float* __restrict__ Bw,     // packed weights
                    const float* __restrict__ bias,   // [E][N]
                    float* __restrict__ res) {
    extern __shared__ char smem[];
    const uint32_t sb = smem_u32(smem);
    const int tid = threadIdx.x;
    const int lane = tid & 31;
    const int e = blockIdx.z, by = blockIdx.y, bx = blockIdx.x;

    constexpr int KDIM = G1 ? DDIM : HDIM;
    constexpr int NTOT = G1 ? HDIM : DDIM;
    constexpr int KI = KDIM / 32;
    constexpr int RB = 128;
    constexpr int NB = NTOT / 8;

    const float* A = (G1 ? g_xg : g_h) + (size_t)e * KDIM * 1024;
    const float* B = Bw + (size_t)e * KDIM * NTOT;

    if (tid < 128) {
        ((float*)(smem + OFF_BIAS))[tid] = bias[e * NTOT + bx * BN + tid];
        if (!G1) {
            ((int*)(smem + OFF_TOK))[tid] = g_sel[e * KSEL + by * BM + tid];
            ((float*)(smem + OFF_WT))[tid] = g_wts[e * KSEL + by * BM + tid];
        }
    }

    auto load_stage = [&](int kt, int buf) {
        const uint32_t st = sb + OFF_DATA + buf * STAGE_SZ;
#pragma unroll
        for (int i = 0; i < 8; i++) {
            const int c = tid + 256 * i;         // 0..2047
            const int kb = (c >> 8) & 3, inner = c & 255;
            const float* src;
            if (c < 1024)
                src = A + ((size_t)(kt * 4 + kb) * RB + by * 16) * 64 + inner * 4;
            else
                src = B + ((size_t)(kt * 4 + kb) * NB + bx * 16) * 64 + inner * 4;
            cpasync16(st + c * 16, src);
        }
        asm volatile("cp.async.commit_group;" ::: "memory");
    };

    const int wid = tid >> 5;
    const int wm = wid & 1, wn = wid >> 1;
    const int msel = lane >> 3;
    const uint32_t aoff = (uint32_t)(((msel & 1) * 16 + (msel >> 1) * 8 + (lane & 7)));
    const uint32_t boff = (uint32_t)(((msel >> 1) * 16 + (msel & 1) * 8 + (lane & 7)));
    const uint32_t aWarp = (uint32_t)(wm * 8 * 16 + aoff) * 16;
    const uint32_t bWarp = (uint32_t)A_BYTES_S + ((uint32_t)(wn * 4 * 16 + boff) * 16);

    float acc[4][4][4];
#pragma unroll
    for (int i = 0; i < 4; i++)
#pragma unroll
        for (int j = 0; j < 4; j++)
#pragma unroll
            for (int q = 0; q < 4; q++) acc[i][j][q] = 0.f;

    // double-buffered fragment registers
    uint32_t afr[2][4][4], bfr[2][4][2];

    auto load_frags = [&](uint32_t ksb, int pb) {
#pragma unroll
        for (int mt = 0; mt < 4; mt++)
            ldsm_x4(afr[pb][mt], ksb + aWarp + mt * 512);
#pragma unroll
        for (int p = 0; p < 2; p++) {
            uint32_t r[4];
            ldsm_x4(r, ksb + bWarp + p * 512);
            bfr[pb][2 * p][0] = r[0]; bfr[pb][2 * p][1] = r[1];
            bfr[pb][2 * p + 1][0] = r[2]; bfr[pb][2 * p + 1][1] = r[3];
        }
    };

    load_stage(0, 0);
    load_stage(1, 1);

    int buf = 0;
#pragma unroll 1
    for (int kt = 0; kt < KI; kt++) {
        if (kt < KI - 1) asm volatile("cp.async.wait_group 1;" ::: "memory");
        else             asm volatile("cp.async.wait_group 0;" ::: "memory");
        __syncthreads();
        if (kt + 2 < KI) {
            int nb2 = buf + 2; if (nb2 >= STAGES) nb2 -= STAGES;
            load_stage(kt + 2, nb2);
        }
        const uint32_t st = sb + OFF_DATA + buf * STAGE_SZ;
        load_frags(st, 0);
#pragma unroll
        for (int ks = 0; ks < 4; ks++) {
            const int cur = ks & 1;
            if (ks < 3) load_frags(st + (ks + 1) * 4096, cur ^ 1);
#pragma unroll
            for (int mt = 0; mt < 4; mt++)
#pragma unroll
                for (int nt = 0; nt < 4; nt++)
                    mma_16n8k8(acc[mt][nt], afr[cur][mt], bfr[cur][nt]);
        }
        if (++buf == STAGES) buf = 0;
    }

    const float* sbias = (const float*)(smem + OFF_BIAS);
    if (G1) {
        // ---- direct epilogue: bias+gelu+rna in regs, float2 stores to packed g_h ----
        // column pair for (nt): cc = wn*32 + nt*8 + (lane&3)*2; row: wm*64+mt*16+(lane>>2)(+8)
        float2 bv[4];
#pragma unroll
        for (int nt = 0; nt < 4; nt++) {
            const int cc = wn * 32 + nt * 8 + (lane & 3) * 2;
            bv[nt] = *(const float2*)&sbias[cc];
        }
        const int rr = lane >> 2;                       // m & 7
#pragma unroll
        for (int mt = 0; mt < 4; mt++) {
            const int m0 = by * BM + wm * 64 + mt * 16 + rr;
            const int rb0 = m0 >> 3;                    // rr == m0 & 7
#pragma unroll
            for (int nt = 0; nt < 4; nt++) {
                const int n = bx * BN + wn * 32 + nt * 8 + (lane & 3) * 2;
                const int kb = n >> 3, h = (n >> 2) & 1, kk = n & 3;
                const size_t base =
                    ((((size_t)e * 512 + kb) * 128 + rb0) * 2 + h) * 32 + rr * 4 + kk;
                float2 v0, v1;
                v0.x = tf32_rna(gelu_exact(acc[mt][nt][0] + bv[nt].x));
                v0.y = tf32_rna(gelu_exact(acc[mt][nt][1] + bv[nt].y));
                v1.x = tf32_rna(gelu_exact(acc[mt][nt][2] + bv[nt].x));
                v1.y = tf32_rna(gelu_exact(acc[mt][nt][3] + bv[nt].y));
                *(float2*)(g_h + base) = v0;            // row m0   (rb0, rr)
                *(float2*)(g_h + base + 64) = v1;       // row m0+8 (rb0+1): +2*32 floats
            }
        }
    } else {
        // ---- staged epilogue + red.v4 scatter ----
        __syncthreads();
        float* Cs = (float*)(smem + OFF_DATA);
#pragma unroll
        for (int mt = 0; mt < 4; mt++)
#pragma unroll
            for (int nt = 0; nt < 4; nt++) {
                const int r0 = wm * 64 + mt * 16 + (lane >> 2);
                const int cc = wn * 32 + nt * 8 + (lane & 3) * 2;
                *(float2*)&Cs[r0 * LDC + cc]       = make_float2(acc[mt][nt][0], acc[mt][nt][1]);
                *(float2*)&Cs[(r0 + 8) * LDC + cc] = make_float2(acc[mt][nt][2], acc[mt][nt][3]);
            }
        __syncthreads();

        const int* tok = (const int*)(smem + OFF_TOK);
        const float* wts = (const float*)(smem + OFF_WT);
#pragma unroll
        for (int q = 0; q < 16; q++) {
            const int v = tid * 16 + q;
            const int r = v >> 5, c4 = (v & 31) * 4;
            float4 c = *(const float4*)(Cs + r * LDC + c4);
            const float g = wts[r];
            float* dst = res + (size_t)tok[r] * DDIM + bx * BN + c4;
            red_add_v4(dst,
                       (c.x + sbias[c4 + 0]) * g,
                       (c.y + sbias[c4 + 1]) * g,
                       (c.z + sbias[c4 + 2]) * g,
                       (c.w + sbias[c4 + 3]) * g);
        }
    }
}

// ================= launch =================
extern "C" void kernel_launch(void* const* d_in, const int* in_sizes, int n_in,
                              void* d_out, int out_size) {
    const float* x  = (const float*)d_in[0];
    const float* rw = (const float*)d_in[1];
    const float* w1 = (const float*)d_in[2];
    const float* b1 = (const float*)d_in[3];
    const float* w2 = (const float*)d_in[4];
    const float* b2 = (const float*)d_in[5];

    float* out = (float*)d_out;
    float* res = out;
    float* logits_out = nullptr;
    float* sel_out = nullptr;
    const long long TD = (long long)T_TOK * DDIM;
    if (out_size >= TD + T_TOK * NEXP) logits_out = out + TD;
    if (out_size >= TD + T_TOK * NEXP + NEXP * KSEL) sel_out = out + TD + T_TOK * NEXP;

    static cudaStream_t sw1 = nullptr, sw2 = nullptr;
    static cudaEvent_t ev0 = nullptr, ev1 = nullptr, ev2 = nullptr, ev3 = nullptr;
    if (!sw1) {
        cudaStreamCreateWithFlags(&sw1, cudaStreamNonBlocking);
        cudaStreamCreateWithFlags(&sw2, cudaStreamNonBlocking);
        cudaEventCreateWithFlags(&ev0, cudaEventDisableTiming);
        cudaEventCreateWithFlags(&ev1, cudaEventDisableTiming);
        cudaEventCreateWithFlags(&ev2, cudaEventDisableTiming);
        cudaEventCreateWithFlags(&ev3, cudaEventDisableTiming);
    }

    float* w1r; cudaGetSymbolAddress((void**)&w1r, g_w1r);
    float* w2r; cudaGetSymbolAddress((void**)&w2r, g_w2r);

    cudaFuncSetAttribute(moe_mma_kernel<true>,
                         cudaFuncAttributeMaxDynamicSharedMemorySize, GEMM_SMEM);
    cudaFuncSetAttribute(moe_mma_kernel<false>,
                         cudaFuncAttributeMaxDynamicSharedMemorySize, GEMM_SMEM);

    // fork: pack_w1 -> pack_w2 serialized on sw1 (pack_w1 gets full bandwidth
    // so GEMM1's gate clears inside the router/topk shadow); memset(res) on sw2.
    cudaEventRecord(ev0, 0);
    cudaStreamWaitEvent(sw1, ev0, 0);
    cudaStreamWaitEvent(sw2, ev0, 0);
    pack_w_kernel<<<dim3(HDIM / 32, DDIM / 32, NEXP), dim3(32, 8), 0, sw1>>>(w1, w1r, DDIM, HDIM);
    cudaEventRecord(ev1, sw1);                 // w1r ready
    pack_w_kernel<<<dim3(DDIM / 32, HDIM / 32, NEXP), dim3(32, 8), 0, sw1>>>(w2, w2r, HDIM, DDIM);
    cudaEventRecord(ev2, sw1);                 // w2r ready
    cudaMemsetAsync(res, 0, (size_t)TD * sizeof(float), sw2);
    cudaEventRecord(ev3, sw2);                 // res zeroed

    // main stream: router -> topk (sort + merge tree) -> gather
    router_kernel<<<T_TOK, 256>>>(x, rw, logits_out);
    sort1024_kernel<<<64, 512>>>();
    merge_tree_kernel<<<NEXP, 512>>>(sel_out);
    gather_x_kernel<<<NEXP * KSEL, 256>>>(x);

    // GEMM1 then GEMM2
    cudaStreamWaitEvent(0, ev1, 0);
    moe_mma_kernel<true><<<dim3(HDIM / BN, KSEL / BM, NEXP), 256, GEMM_SMEM>>>(w1r, b1, nullptr);
    cudaStreamWaitEvent(0, ev2, 0);
    cudaStreamWaitEvent(0, ev3, 0);
    moe_mma_kernel<false><<<dim3(DDIM / BN, KSEL / BM, NEXP), 256, GEMM_SMEM>>>(w2r, b2, res);
}